// round 12
// baseline (speedup 1.0000x reference)
#include <cuda_runtime.h>
#include <cstdint>

// Problem constants (match reference)
#define NUM_MOVABLE 10000000
#define NUM_PHYS    11000000
#define BXD 32
#define BYD 32
#define NBINS (BXD * BYD)

#define HIST_BLOCKS 1184   // 8 CTAs/SM on 148 SMs -> full occupancy
#define HIST_THREADS 256
#define NREP 8             // L2 replica accumulators

// Global scratch accumulators (no cudaMalloc allowed).
// Zero-initialized at module load; the finishing block resets them after
// consuming (atomicExch), so "all zero on entry" holds across graph replays.
// Widened format: low32 | (high32 << 32), fields in 1/512 fixed point.
// gA/g2A: S | Sx.   gB/g2B: Sy | Sxy.
__device__ unsigned long long gA[NBINS];
__device__ unsigned long long gB[NBINS];
__device__ unsigned long long g2A[NREP][NBINS];
__device__ unsigned long long g2B[NREP][NBINS];
__device__ unsigned int g_ctr;   // wraps back to 0 every full grid

// Moments at source bin (iy,ix):  S += a, Sx += a*dx, Sy += a*dy, Sxy += a*dx*dy.
// density(j,i) = (S-Sx-Sy+Sxy)[j,i] + (Sx-Sxy)[j,i-1] + (Sy-Sxy)[j-1,i] + Sxy[j-1,i-1].
__global__ void __launch_bounds__(HIST_THREADS, 8)
fused_kernel(const float4* __restrict__ x4,
             const float4* __restrict__ y4,
             const int4*   __restrict__ m4,    // mask is int32 per element
             const float4* __restrict__ sx4,
             const float4* __restrict__ sy4,
             float* __restrict__ out) {
    __shared__ unsigned long long sh[NBINS];   // 4x16-bit: S,adx,ady,adxy (1/512)
    __shared__ float tail2[2 * NBINS];         // tail only: CY | CXY
    for (int i = threadIdx.x; i < NBINS; i += HIST_THREADS) sh[i] = 0ull;
    __syncthreads();

    const float CLMP  = 30.9999990463f;        // float(31 - 1e-6)
    const float MAGIC = 8388608.0f;            // 2^23, RNE-to-integer trick
    const int   rep   = blockIdx.x & (NREP - 1);

    const int n4 = NUM_MOVABLE / 4;            // 2,500,000 exact
    for (int i = blockIdx.x * HIST_THREADS + threadIdx.x; i < n4;
         i += HIST_BLOCKS * HIST_THREADS) {
        float4 x  = __ldg(x4  + i);
        float4 y  = __ldg(y4  + i);
        float4 sx = __ldg(sx4 + i);
        float4 sy = __ldg(sy4 + i);
        int4   m  = __ldg(m4  + i);

        #pragma unroll
        for (int k = 0; k < 4; k++) {
            float xv  = (k == 0) ? x.x  : (k == 1) ? x.y  : (k == 2) ? x.z  : x.w;
            float yv  = (k == 0) ? y.x  : (k == 1) ? y.y  : (k == 2) ? y.z  : y.w;
            float sxv = (k == 0) ? sx.x : (k == 1) ? sx.y : (k == 2) ? sx.z : sx.w;
            float syv = (k == 0) ? sy.x : (k == 1) ? sy.y : (k == 2) ? sy.z : sy.w;
            int   mv  = (k == 0) ? m.x  : (k == 1) ? m.y  : (k == 2) ? m.z  : m.w;

            float fx = fminf(fmaxf(xv * 32.0f, 0.0f), CLMP);
            float fy = fminf(fmaxf(yv * 32.0f, 0.0f), CLMP);
            unsigned qx = __float_as_uint(fmaf(fx, 65536.0f, MAGIC)) & 0x3FFFFF;
            unsigned qy = __float_as_uint(fmaf(fy, 65536.0f, MAGIC)) & 0x3FFFFF;

            float a = fminf(sxv * 32.0f, 1.0f) * fminf(syv * 32.0f, 1.0f);
            if (mv == 0) a = 0.0f;
            unsigned a512 = __float_as_uint(fmaf(a, 512.0f, MAGIC)) & 0xFFFF;

            unsigned dxq = qx & 0xFFFFu;       // dx in 2^-16 units
            unsigned dyq = qy & 0xFFFFu;
            unsigned ix  = qx >> 16;           // 0..31
            unsigned iy  = qy >> 16;
            int bin = iy * BXD + ix;

            unsigned adx  = (a512 * dxq + 32768u) >> 16;   // round(a*dx*512)
            unsigned ady  = (a512 * dyq + 32768u) >> 16;
            unsigned adxy = (adx  * dyq + 32768u) >> 16;

            if ((k & 1) == 0) {
                // shared-memory path: one packed u64 ATOMS
                unsigned long long v =
                    (unsigned long long)(a512 | (adx << 16)) |
                    ((unsigned long long)(ady | (adxy << 16)) << 32);
                atomicAdd(&sh[bin], v);
            } else {
                // L2 path: widened format, 2 REDG.64 into a replica array
                unsigned long long A =
                    (unsigned long long)a512 | ((unsigned long long)adx << 32);
                unsigned long long B =
                    (unsigned long long)ady  | ((unsigned long long)adxy << 32);
                atomicAdd(&g2A[rep][bin], A);
                atomicAdd(&g2B[rep][bin], B);
            }
        }
    }
    __syncthreads();

    // Flush smem histogram: widen 16-bit fields to 32-bit, 2 u64 atomics/bin.
    for (int i = threadIdx.x; i < NBINS; i += HIST_THREADS) {
        unsigned long long v = sh[i];
        if (v != 0ull) {
            unsigned long long A = (v & 0xFFFFull) |
                                   (((v >> 16) & 0xFFFFull) << 32);
            unsigned long long B = ((v >> 32) & 0xFFFFull) |
                                   (((v >> 48) & 0xFFFFull) << 32);
            atomicAdd(&gA[i], A);
            atomicAdd(&gB[i], B);
        }
    }
    __threadfence();
    __syncthreads();

    // Last-block-done detection; atomicInc wraps back to 0 for next replay.
    __shared__ unsigned int is_last;
    if (threadIdx.x == 0) {
        unsigned old = atomicInc(&g_ctr, HIST_BLOCKS - 1);
        is_last = (old == HIST_BLOCKS - 1) ? 1u : 0u;
    }
    __syncthreads();
    if (!is_last) return;

    // ---- finishing block: merge accumulators, reconstruct density, var ----
    float* sf = (float*)sh;   // reuse: sf[2b]=C00, sf[2b+1]=CX
    const float inv = 1.0f / 512.0f;
    for (int i = threadIdx.x; i < NBINS; i += HIST_THREADS) {
        // atomicExch = coherent read of other blocks' results + reset in one op.
        unsigned long long A = atomicExch(&gA[i], 0ull);
        unsigned long long B = atomicExch(&gB[i], 0ull);
        #pragma unroll
        for (int r = 0; r < NREP; r++) {
            A += atomicExch(&g2A[r][i], 0ull);
            B += atomicExch(&g2B[r][i], 0ull);
        }
        float S   = (float)(unsigned)(A & 0xFFFFFFFFull) * inv;
        float Sx  = (float)(unsigned)(A >> 32)           * inv;
        float Sy  = (float)(unsigned)(B & 0xFFFFFFFFull) * inv;
        float Sxy = (float)(unsigned)(B >> 32)           * inv;
        sf[2 * i]        = S - Sx - Sy + Sxy;   // C00
        sf[2 * i + 1]    = Sx - Sxy;            // CX
        tail2[i]         = Sy - Sxy;            // CY
        tail2[NBINS + i] = Sxy;                 // CXY
    }
    __syncthreads();

    // Pass 1: density + sum (density kept in registers, 4 bins/thread)
    float vreg[NBINS / HIST_THREADS];
    float local_sum = 0.0f;
    #pragma unroll
    for (int r = 0; r < NBINS / HIST_THREADS; r++) {
        int b = threadIdx.x + r * HIST_THREADS;
        int i = b & 31, j = b >> 5;
        float v = sf[2 * b];
        if (i > 0)          v += sf[2 * (b - 1) + 1];
        if (j > 0)          v += tail2[b - 32];
        if (i > 0 && j > 0) v += tail2[NBINS + b - 33];
        vreg[r] = v;
        local_sum += v;
    }

    __shared__ float red[8];
    __shared__ float mean_sh;
    int lane = threadIdx.x & 31;
    int wid  = threadIdx.x >> 5;

    float s = local_sum;
    #pragma unroll
    for (int off = 16; off > 0; off >>= 1)
        s += __shfl_xor_sync(0xFFFFFFFFu, s, off);
    if (lane == 0) red[wid] = s;
    __syncthreads();
    if (threadIdx.x == 0) {
        float t = 0.0f;
        #pragma unroll
        for (int w = 0; w < 8; w++) t += red[w];
        mean_sh = t * (1.0f / (float)NBINS);
    }
    __syncthreads();

    // Pass 2: sum of squared deviations
    float mean = mean_sh;
    float local_q = 0.0f;
    #pragma unroll
    for (int r = 0; r < NBINS / HIST_THREADS; r++) {
        float d = vreg[r] - mean;
        local_q = fmaf(d, d, local_q);
    }
    float q = local_q;
    #pragma unroll
    for (int off = 16; off > 0; off >>= 1)
        q += __shfl_xor_sync(0xFFFFFFFFu, q, off);
    __syncthreads();
    if (lane == 0) red[wid] = q;
    __syncthreads();
    if (threadIdx.x == 0) {
        float t = 0.0f;
        #pragma unroll
        for (int w = 0; w < 8; w++) t += red[w];
        out[0] = t * (1.0f / (float)(NBINS - 1));   // ddof=1
    }
}

extern "C" void kernel_launch(void* const* d_in, const int* in_sizes, int n_in,
                              void* d_out, int out_size) {
    const float* pos  = (const float*)d_in[0];
    const int*   mask = (const int*)d_in[1];      // jax bool -> int32 in harness
    const float* msx  = (const float*)d_in[2];
    const float* msy  = (const float*)d_in[3];

    const float4* x4  = (const float4*)(pos);               // pos[0 : 10M)
    const float4* y4  = (const float4*)(pos + NUM_PHYS);    // pos[11M : 21M), 16B aligned
    const int4*   m4  = (const int4*)(mask);
    const float4* sx4 = (const float4*)(msx);
    const float4* sy4 = (const float4*)(msy);

    fused_kernel<<<HIST_BLOCKS, HIST_THREADS>>>(x4, y4, m4, sx4, sy4,
                                                (float*)d_out);
}

// round 17
// speedup vs baseline: 2.6493x; 2.6493x over previous
#include <cuda_runtime.h>
#include <cstdint>

// Problem constants (match reference)
#define NUM_MOVABLE 10000000
#define NUM_PHYS    11000000
#define BXD 32
#define BYD 32
#define NBINS (BXD * BYD)

#define HIST_BLOCKS 888    // 6 CTAs/SM on 148 SMs (regs budget 42 -> MLP 10)
#define HIST_THREADS 256
#define GSTRIDE (HIST_BLOCKS * HIST_THREADS)

// Global scratch accumulators (no cudaMalloc allowed).
// Zero-initialized at module load; the finishing block resets them after
// consuming (atomicExch), so "all zero on entry" holds across graph replays.
// Widened format: low32 | (high32 << 32), fields in 1/512 fixed point.
// gA: S | Sx.   gB: Sy | Sxy.
__device__ unsigned long long gA[NBINS];
__device__ unsigned long long gB[NBINS];
__device__ unsigned int g_ctr;   // wraps back to 0 every full grid

struct Packed { unsigned long long v; int bin; };

// Moments at source bin (iy,ix):  S += a, Sx += a*dx, Sy += a*dy, Sxy += a*dx*dy.
// density(j,i) = (S-Sx-Sy+Sxy)[j,i] + (Sx-Sxy)[j,i-1] + (Sy-Sxy)[j-1,i] + Sxy[j-1,i-1].
__device__ __forceinline__ Packed pack_elem(float xv, float yv,
                                            float sxv, float syv, int mv) {
    const float CLMP  = 30.9999990463f;        // float(31 - 1e-6)
    const float MAGIC = 8388608.0f;            // 2^23, RNE-to-integer trick

    float fx = fminf(fmaxf(xv * 32.0f, 0.0f), CLMP);
    float fy = fminf(fmaxf(yv * 32.0f, 0.0f), CLMP);
    unsigned qx = __float_as_uint(fmaf(fx, 65536.0f, MAGIC)) & 0x3FFFFF;
    unsigned qy = __float_as_uint(fmaf(fy, 65536.0f, MAGIC)) & 0x3FFFFF;

    float a = fminf(sxv * 32.0f, 1.0f) * fminf(syv * 32.0f, 1.0f);
    if (mv == 0) a = 0.0f;
    unsigned a512 = __float_as_uint(fmaf(a, 512.0f, MAGIC)) & 0xFFFF;

    unsigned dxq = qx & 0xFFFFu;               // dx in 2^-16 units
    unsigned dyq = qy & 0xFFFFu;

    unsigned adx  = (a512 * dxq + 32768u) >> 16;   // round(a*dx*512)
    unsigned ady  = (a512 * dyq + 32768u) >> 16;
    unsigned adxy = (adx  * dyq + 32768u) >> 16;

    Packed p;
    p.v = (unsigned long long)(a512 | (adx << 16)) |
          ((unsigned long long)(ady | (adxy << 16)) << 32);
    p.bin = (int)((qy >> 16) * BXD + (qx >> 16));
    return p;
}

__global__ void __launch_bounds__(HIST_THREADS, 6)
fused_kernel(const float4* __restrict__ x4,
             const float4* __restrict__ y4,
             const int4*   __restrict__ m4,    // mask is int32 per element
             const float4* __restrict__ sx4,
             const float4* __restrict__ sy4,
             float* __restrict__ out) {
    __shared__ unsigned long long sh[NBINS];   // 4x16-bit: S,adx,ady,adxy (1/512)
    __shared__ float tail2[2 * NBINS];         // finisher only: CY | CXY
    for (int i = threadIdx.x; i < NBINS; i += HIST_THREADS) sh[i] = 0ull;
    __syncthreads();

    const int n4 = NUM_MOVABLE / 4;            // 2,500,000 exact

    for (int i = blockIdx.x * HIST_THREADS + threadIdx.x; i < n4;
         i += 2 * GSTRIDE) {
        int j = i + GSTRIDE;
        bool hasj = (j < n4);

        // Issue all loads up front: up to 10 outstanding LDG.128
        float4 xa  = __ldg(x4  + i);
        float4 ya  = __ldg(y4  + i);
        float4 sxa = __ldg(sx4 + i);
        float4 sya = __ldg(sy4 + i);
        int4   ma  = __ldg(m4  + i);
        int jj = hasj ? j : i;                 // safe dummy to keep loads unconditional
        float4 xb  = __ldg(x4  + jj);
        float4 yb  = __ldg(y4  + jj);
        float4 sxb = __ldg(sx4 + jj);
        float4 syb = __ldg(sy4 + jj);
        int4   mb  = __ldg(m4  + jj);
        if (!hasj) { mb.x = 0; mb.y = 0; mb.z = 0; mb.w = 0; }  // mask off dup

        Packed p0 = pack_elem(xa.x, ya.x, sxa.x, sya.x, ma.x);
        Packed p1 = pack_elem(xa.y, ya.y, sxa.y, sya.y, ma.y);
        Packed p2 = pack_elem(xa.z, ya.z, sxa.z, sya.z, ma.z);
        Packed p3 = pack_elem(xa.w, ya.w, sxa.w, sya.w, ma.w);
        Packed q0 = pack_elem(xb.x, yb.x, sxb.x, syb.x, mb.x);
        Packed q1 = pack_elem(xb.y, yb.y, sxb.y, syb.y, mb.y);
        Packed q2 = pack_elem(xb.z, yb.z, sxb.z, syb.z, mb.z);
        Packed q3 = pack_elem(xb.w, yb.w, sxb.w, syb.w, mb.w);

        atomicAdd(&sh[p0.bin], p0.v);
        atomicAdd(&sh[p1.bin], p1.v);
        atomicAdd(&sh[p2.bin], p2.v);
        atomicAdd(&sh[p3.bin], p3.v);
        atomicAdd(&sh[q0.bin], q0.v);
        atomicAdd(&sh[q1.bin], q1.v);
        atomicAdd(&sh[q2.bin], q2.v);
        atomicAdd(&sh[q3.bin], q3.v);
    }
    __syncthreads();

    // Flush smem histogram: widen 16-bit fields to 32-bit, 2 u64 atomics/bin.
    // Global per-field totals <= ~2e7 << 2^32: no cross-field carry.
    for (int i = threadIdx.x; i < NBINS; i += HIST_THREADS) {
        unsigned long long v = sh[i];
        if (v != 0ull) {
            unsigned long long A = (v & 0xFFFFull) |
                                   (((v >> 16) & 0xFFFFull) << 32);
            unsigned long long B = ((v >> 32) & 0xFFFFull) |
                                   (((v >> 48) & 0xFFFFull) << 32);
            atomicAdd(&gA[i], A);
            atomicAdd(&gB[i], B);
        }
    }
    __threadfence();
    __syncthreads();

    // Last-block-done detection; atomicInc wraps back to 0 for next replay.
    __shared__ unsigned int is_last;
    if (threadIdx.x == 0) {
        unsigned old = atomicInc(&g_ctr, HIST_BLOCKS - 1);
        is_last = (old == HIST_BLOCKS - 1) ? 1u : 0u;
    }
    __syncthreads();
    if (!is_last) return;

    // ---- finishing block: merge accumulators, reconstruct density, var ----
    float* sf = (float*)sh;   // reuse: sf[2b]=C00, sf[2b+1]=CX
    const float inv = 1.0f / 512.0f;
    for (int i = threadIdx.x; i < NBINS; i += HIST_THREADS) {
        // atomicExch = coherent read of other blocks' results + reset in one op.
        unsigned long long A = atomicExch(&gA[i], 0ull);
        unsigned long long B = atomicExch(&gB[i], 0ull);
        float S   = (float)(unsigned)(A & 0xFFFFFFFFull) * inv;
        float Sx  = (float)(unsigned)(A >> 32)           * inv;
        float Sy  = (float)(unsigned)(B & 0xFFFFFFFFull) * inv;
        float Sxy = (float)(unsigned)(B >> 32)           * inv;
        sf[2 * i]        = S - Sx - Sy + Sxy;   // C00
        sf[2 * i + 1]    = Sx - Sxy;            // CX
        tail2[i]         = Sy - Sxy;            // CY
        tail2[NBINS + i] = Sxy;                 // CXY
    }
    __syncthreads();

    // Pass 1: density + sum (density kept in registers, 4 bins/thread)
    float vreg[NBINS / HIST_THREADS];
    float local_sum = 0.0f;
    #pragma unroll
    for (int r = 0; r < NBINS / HIST_THREADS; r++) {
        int b = threadIdx.x + r * HIST_THREADS;
        int i = b & 31, j = b >> 5;
        float v = sf[2 * b];
        if (i > 0)          v += sf[2 * (b - 1) + 1];
        if (j > 0)          v += tail2[b - 32];
        if (i > 0 && j > 0) v += tail2[NBINS + b - 33];
        vreg[r] = v;
        local_sum += v;
    }

    __shared__ float red[8];
    __shared__ float mean_sh;
    int lane = threadIdx.x & 31;
    int wid  = threadIdx.x >> 5;

    float s = local_sum;
    #pragma unroll
    for (int off = 16; off > 0; off >>= 1)
        s += __shfl_xor_sync(0xFFFFFFFFu, s, off);
    if (lane == 0) red[wid] = s;
    __syncthreads();
    if (threadIdx.x == 0) {
        float t = 0.0f;
        #pragma unroll
        for (int w = 0; w < 8; w++) t += red[w];
        mean_sh = t * (1.0f / (float)NBINS);
    }
    __syncthreads();

    // Pass 2: sum of squared deviations
    float mean = mean_sh;
    float local_q = 0.0f;
    #pragma unroll
    for (int r = 0; r < NBINS / HIST_THREADS; r++) {
        float d = vreg[r] - mean;
        local_q = fmaf(d, d, local_q);
    }
    float q = local_q;
    #pragma unroll
    for (int off = 16; off > 0; off >>= 1)
        q += __shfl_xor_sync(0xFFFFFFFFu, q, off);
    __syncthreads();
    if (lane == 0) red[wid] = q;
    __syncthreads();
    if (threadIdx.x == 0) {
        float t = 0.0f;
        #pragma unroll
        for (int w = 0; w < 8; w++) t += red[w];
        out[0] = t * (1.0f / (float)(NBINS - 1));   // ddof=1
    }
}

extern "C" void kernel_launch(void* const* d_in, const int* in_sizes, int n_in,
                              void* d_out, int out_size) {
    const float* pos  = (const float*)d_in[0];
    const int*   mask = (const int*)d_in[1];      // jax bool -> int32 in harness
    const float* msx  = (const float*)d_in[2];
    const float* msy  = (const float*)d_in[3];

    const float4* x4  = (const float4*)(pos);               // pos[0 : 10M)
    const float4* y4  = (const float4*)(pos + NUM_PHYS);    // pos[11M : 21M), 16B aligned
    const int4*   m4  = (const int4*)(mask);
    const float4* sx4 = (const float4*)(msx);
    const float4* sy4 = (const float4*)(msy);

    fused_kernel<<<HIST_BLOCKS, HIST_THREADS>>>(x4, y4, m4, sx4, sy4,
                                                (float*)d_out);
}